// round 2
// baseline (speedup 1.0000x reference)
#include <cuda_runtime.h>
#include <cuda_bf16.h>
#include <cstdint>

#define BB 32
#define TT 800
#define LL 60
#define HH 512
#define DD 1024
#define AA 512
#define FCN 16
#define KCV 101
#define CC 4000

// ---------------- static device scratch ----------------
__device__ float g_hE[BB * TT * AA];        // [b*T+t][a]
__device__ float g_recpre[BB * LL * 2048];  // [(b*L+l)][j]  targets@W_ys^T + b_gs
__device__ float g_Wscat[3072 * 512];       // rows: [W_se(512); W_sy(512); W_ss(2048)]
__device__ float g_Wgcat[2560 * 1024];      // rows: [W_gy(512); W_gs(2048)]
__device__ float g_spart[2 * BB * 3072];    // K-split partials of s @ Wscat^T
__device__ float g_gpart[4 * BB * 2560];    // K-split partials of g @ Wgcat^T
__device__ float g_gp2[4 * BB * DD];        // t-split partials of alpha @ hbatch
__device__ float g_e[BB * TT];
__device__ float g_alpha[BB * TT];
__device__ float g_ypre[BB * HH];
__device__ float g_s[BB * HH];
__device__ float g_c[BB * HH];

__device__ __forceinline__ float tanh_fast(float x) {
    float e2 = __expf(2.f * x);
    return 1.f - 2.f / (e2 + 1.f);
}
__device__ __forceinline__ float sig_acc(float x) {   // == reference _sig
    return tanhf(0.5f * x) * 0.5f + 0.5f;
}

// ---------------- init: zero state, build concatenated weights ----------------
__global__ void k_init(const float* __restrict__ W_se, const float* __restrict__ W_sy,
                       const float* __restrict__ W_ss, const float* __restrict__ W_gy,
                       const float* __restrict__ W_gs) {
    int i0 = blockIdx.x * blockDim.x + threadIdx.x;
    int st = gridDim.x * blockDim.x;
    for (int i = i0; i < BB * HH; i += st) { g_s[i] = 0.f; g_c[i] = 0.f; }
    for (int i = i0; i < BB * TT; i += st) g_alpha[i] = 0.f;
    for (int i = i0; i < 3072 * 512; i += st) {
        int r = i >> 9, k = i & 511;
        float v;
        if (r < 512)       v = W_se[i];
        else if (r < 1024) v = W_sy[(r - 512) * 512 + k];
        else               v = W_ss[(r - 1024) * 512 + k];
        g_Wscat[i] = v;
    }
    for (int i = i0; i < 2560 * 1024; i += st) {
        int r = i >> 10, k = i & 1023;
        g_Wgcat[i] = (r < 512) ? W_gy[i] : W_gs[(r - 512) * 1024 + k];
    }
}

// ---------------- big GEMM: Out[M,N] = A[M,K] @ W[N,K]^T (+bias) ----------------
// 128x128 tile, 256 threads, 8x8 micro, KC=16. M%128==0, N%128==0, K%16==0.
template <int MODE>  // 0: Out=g_hE  1: Out=g_recpre (+bias)
__global__ __launch_bounds__(256) void k_gemm_big(
    const float* __restrict__ A, const float* __restrict__ W,
    const float* __restrict__ bias, int lda, int ldw, int ldo, int K) {
    __shared__ __align__(16) float As[16][132];
    __shared__ __align__(16) float Bs[16][132];
    float* Out = (MODE == 0) ? g_hE : g_recpre;
    int t = threadIdx.x;
    int n0 = blockIdx.x * 128, m0 = blockIdx.y * 128;
    int tr = t >> 4, tc = t & 15;
    float acc[8][8];
#pragma unroll
    for (int i = 0; i < 8; i++)
#pragma unroll
        for (int j = 0; j < 8; j++) acc[i][j] = 0.f;

    for (int k0 = 0; k0 < K; k0 += 16) {
#pragma unroll
        for (int i = 0; i < 8; i++) {
            int e = t + i * 256;
            int m = e >> 4, k = e & 15;
            As[k][m] = A[(size_t)(m0 + m) * lda + k0 + k];
            Bs[k][m] = W[(size_t)(n0 + m) * ldw + k0 + k];
        }
        __syncthreads();
#pragma unroll
        for (int k = 0; k < 16; k++) {
            float4 a0 = *(const float4*)&As[k][tr * 8];
            float4 a1 = *(const float4*)&As[k][tr * 8 + 4];
            float4 b0 = *(const float4*)&Bs[k][tc * 8];
            float4 b1 = *(const float4*)&Bs[k][tc * 8 + 4];
            float av[8] = {a0.x, a0.y, a0.z, a0.w, a1.x, a1.y, a1.z, a1.w};
            float bv[8] = {b0.x, b0.y, b0.z, b0.w, b1.x, b1.y, b1.z, b1.w};
#pragma unroll
            for (int i = 0; i < 8; i++)
#pragma unroll
                for (int j = 0; j < 8; j++) acc[i][j] = fmaf(av[i], bv[j], acc[i][j]);
        }
        __syncthreads();
    }
#pragma unroll
    for (int i = 0; i < 8; i++) {
        int m = m0 + tr * 8 + i;
#pragma unroll
        for (int j = 0; j < 8; j++) {
            int n = n0 + tc * 8 + j;
            float v = acc[i][j];
            if (MODE == 1) v += bias[n];
            Out[(size_t)m * ldo + n] = v;
        }
    }
}

// ---------------- skinny GEMM: M=32, Out = A @ W^T, K-split partials ----------------
// MODE 0: scat = s @ Wscat^T   (N=3072, K=512,  split 2) -> g_spart
// MODE 1: gcat = g @ Wgcat^T   (N=2560, K=1024, split 4) -> g_gpart, A = sum of 4 partials
// MODE 2: y    = ypre @ W_yy^T (N=4000, K=512,  split 1) -> d_out (+b_yy)
template <int MODE>
__global__ __launch_bounds__(256) void k_skinny(const float* __restrict__ Wext,
                                                const float* __restrict__ bias,
                                                float* __restrict__ outext) {
    constexpr int N = (MODE == 0) ? 3072 : (MODE == 1) ? 2560 : 4000;
    constexpr int K = (MODE == 1) ? 1024 : 512;
    constexpr int NSPLIT = (MODE == 0) ? 2 : (MODE == 1) ? 4 : 1;
    constexpr int lda = (MODE == 1) ? 1024 : 512;
    constexpr int KS = K / NSPLIT;
    constexpr int NPART = (MODE == 1) ? 4 : 1;
    __shared__ __align__(16) float As[32][36];
    __shared__ float Bs[32][65];
    int t = threadIdx.x;
    int n0 = blockIdx.x * 64;
    int z = blockIdx.y;
    const float* A = (MODE == 0) ? g_s : (MODE == 1) ? g_gp2 : g_ypre;
    const float* W = (MODE == 0) ? g_Wscat : (MODE == 1) ? g_Wgcat : Wext;
    float* Out;
    int rs;
    if (MODE == 0)      { Out = g_spart + z * BB * 3072; rs = 3072; }
    else if (MODE == 1) { Out = g_gpart + z * BB * 2560; rs = 2560; }
    else                { Out = outext;                  rs = LL * CC; }
    int tm = t & 3, tn = t >> 2;
    float acc[8];
#pragma unroll
    for (int i = 0; i < 8; i++) acc[i] = 0.f;
    int kbase = z * KS;

    for (int kk = 0; kk < KS; kk += 32) {
        int k0 = kbase + kk;
#pragma unroll
        for (int j = 0; j < 4; j++) {
            int e = t + j * 256;
            int m = e >> 5, k = e & 31;
            float v = 0.f;
#pragma unroll
            for (int p = 0; p < NPART; p++) v += A[p * BB * lda + m * lda + k0 + k];
            As[k][m] = v;
        }
#pragma unroll
        for (int j = 0; j < 8; j++) {
            int e = t + j * 256;
            int n = e >> 5, k = e & 31;
            float v = 0.f;
            if (MODE != 2 || (n0 + n) < N) v = W[(size_t)(n0 + n) * K + k0 + k];
            Bs[k][n] = v;
        }
        __syncthreads();
#pragma unroll
        for (int k = 0; k < 32; k++) {
            float4 a0 = *(const float4*)&As[k][tm * 8];
            float4 a1 = *(const float4*)&As[k][tm * 8 + 4];
            float bv = Bs[k][tn];
            acc[0] = fmaf(a0.x, bv, acc[0]);
            acc[1] = fmaf(a0.y, bv, acc[1]);
            acc[2] = fmaf(a0.z, bv, acc[2]);
            acc[3] = fmaf(a0.w, bv, acc[3]);
            acc[4] = fmaf(a1.x, bv, acc[4]);
            acc[5] = fmaf(a1.y, bv, acc[5]);
            acc[6] = fmaf(a1.z, bv, acc[6]);
            acc[7] = fmaf(a1.w, bv, acc[7]);
        }
        __syncthreads();
    }
    int n = n0 + tn;
    if (MODE != 2 || n < N) {
#pragma unroll
        for (int i = 0; i < 8; i++) {
            float v = acc[i];
            if (MODE == 2) v += bias[n];
            Out[(tm * 8 + i) * rs + n] = v;
        }
    }
}

// ---------------- fused attention scoring: e[b,t] ----------------
__global__ __launch_bounds__(256) void k_attn(const int* __restrict__ lengths,
                                              const float* __restrict__ W_fe,
                                              const float* __restrict__ conv_w,
                                              const float* __restrict__ conv_b,
                                              const float* __restrict__ w_ee) {
    __shared__ float sE_s[AA];
    __shared__ float wee_s[AA];
    __shared__ float convw_s[FCN * KCV];
    __shared__ float convb_s[FCN];
    __shared__ float alpha_s[164];
    __shared__ float Wfe_s[AA * 17];
    int b = blockIdx.y;
    int t0 = blockIdx.x * 64;
    int tid = threadIdx.x;
    for (int a = tid; a < AA; a += 256) {
        sE_s[a] = g_spart[b * 3072 + a] + g_spart[BB * 3072 + b * 3072 + a];
        wee_s[a] = w_ee[a];
    }
    for (int i = tid; i < FCN * KCV; i += 256) convw_s[i] = conv_w[i];
    if (tid < FCN) convb_s[tid] = conv_b[tid];
    for (int i = tid; i < AA * FCN; i += 256) {
        int a = i >> 4, f = i & 15;
        Wfe_s[a * 17 + f] = W_fe[i];
    }
    if (tid < 164) {
        int tg = t0 - 50 + tid;
        alpha_s[tid] = (tg >= 0 && tg < TT) ? g_alpha[b * TT + tg] : 0.f;
    }
    __syncthreads();
    int len = lengths[b];
    int w = tid >> 5, lane = tid & 31;
    for (int tt = w; tt < 64; tt += 8) {
        int tabs = t0 + tt;
        if (tabs >= TT) break;
        if (tabs >= len) {
            if (lane == 0) g_e[b * TT + tabs] = -1e30f;
            continue;
        }
        // conv features for this t: 16 filters, split over 2 half-warps
        int f = lane & 15, half = lane >> 4;
        float yp = 0.f;
        int ks = half * 51;
#pragma unroll
        for (int k2 = 0; k2 < 51; k2++) {
            int k = ks + k2;
            if (k < KCV) yp = fmaf(alpha_s[tt + k], convw_s[f * KCV + k], yp);
        }
        yp += __shfl_down_sync(0xffffffffu, yp, 16);
        if (half == 0) yp += convb_s[f];
        float yv[16];
#pragma unroll
        for (int ff = 0; ff < 16; ff++) yv[ff] = __shfl_sync(0xffffffffu, yp, ff);
        const float* hEr = &g_hE[((size_t)b * TT + tabs) * AA];
        float acc = 0.f;
#pragma unroll
        for (int i = 0; i < 16; i++) {
            int a = i * 32 + lane;
            float v = sE_s[a] + hEr[a];
#pragma unroll
            for (int ff = 0; ff < 16; ff++) v = fmaf(yv[ff], Wfe_s[a * 17 + ff], v);
            acc = fmaf(tanh_fast(v), wee_s[a], acc);
        }
#pragma unroll
        for (int off = 16; off; off >>= 1) acc += __shfl_down_sync(0xffffffffu, acc, off);
        if (lane == 0) g_e[b * TT + tabs] = acc;
    }
}

// ---------------- softmax over t per batch ----------------
__global__ __launch_bounds__(256) void k_softmax() {
    int b = blockIdx.x, tid = threadIdx.x;
    __shared__ float es[TT];
    __shared__ float red[256];
    float mx = -3e38f;
    for (int t2 = tid; t2 < TT; t2 += 256) {
        float v = g_e[b * TT + t2];
        es[t2] = v;
        mx = fmaxf(mx, v);
    }
    red[tid] = mx;
    __syncthreads();
    for (int o = 128; o; o >>= 1) {
        if (tid < o) red[tid] = fmaxf(red[tid], red[tid + o]);
        __syncthreads();
    }
    float M = red[0];
    __syncthreads();
    float sm = 0.f;
    for (int t2 = tid; t2 < TT; t2 += 256) {
        float p = __expf(es[t2] - M);
        es[t2] = p;
        sm += p;
    }
    red[tid] = sm;
    __syncthreads();
    for (int o = 128; o; o >>= 1) {
        if (tid < o) red[tid] += red[tid + o];
        __syncthreads();
    }
    float inv = 1.f / red[0];
    for (int t2 = tid; t2 < TT; t2 += 256) g_alpha[b * TT + t2] = es[t2] * inv;
}

// ---------------- g = alpha @ hbatch (t-split x4 partials) ----------------
__global__ __launch_bounds__(256) void k_gaccum(const float* __restrict__ hbatch,
                                                const int* __restrict__ lengths) {
    int b = blockIdx.y, d0 = blockIdx.x * 128, ts = blockIdx.z;
    int len = lengths[b];
    int t1 = (len * ts) >> 2, t2 = (len * (ts + 1)) >> 2;
    int dl = threadIdx.x & 127, th = threadIdx.x >> 7;
    float acc = 0.f;
    for (int t = t1 + th; t < t2; t += 2)
        acc = fmaf(g_alpha[b * TT + t], hbatch[((size_t)b * TT + t) * DD + d0 + dl], acc);
    __shared__ float red[256];
    red[threadIdx.x] = acc;
    __syncthreads();
    if (th == 0) g_gp2[(ts * BB + b) * DD + d0 + dl] = red[dl] + red[dl + 128];
}

// ---------------- fused activation + LSTM cell ----------------
__global__ __launch_bounds__(512) void k_cell(const float* __restrict__ b_gy, int l) {
    int b = blockIdx.x, h = threadIdx.x;
    float gy = 0.f;
#pragma unroll
    for (int z = 0; z < 4; z++) gy += g_gpart[z * BB * 2560 + b * 2560 + h];
    float sy = g_spart[b * 3072 + 512 + h] + g_spart[BB * 3072 + b * 3072 + 512 + h];
    g_ypre[b * HH + h] = tanhf(gy + sy + b_gy[h]);
    float r[4];
#pragma unroll
    for (int q = 0; q < 4; q++) {
        int j = h + q * 512;
        float v = g_recpre[((size_t)b * LL + l) * 2048 + j];
        v += g_spart[b * 3072 + 1024 + j] + g_spart[BB * 3072 + b * 3072 + 1024 + j];
#pragma unroll
        for (int z = 0; z < 4; z++) v += g_gpart[z * BB * 2560 + b * 2560 + 512 + j];
        r[q] = v;
    }
    float c = sig_acc(r[1]) * g_c[b * HH + h] + sig_acc(r[0]) * tanhf(r[2]);
    float s = sig_acc(r[3]) * tanhf(c);
    g_c[b * HH + h] = c;
    g_s[b * HH + h] = s;
}

// ---------------- launch ----------------
extern "C" void kernel_launch(void* const* d_in, const int* in_sizes, int n_in,
                              void* d_out, int out_size) {
    const float* hbatch  = (const float*)d_in[0];
    const int*   lengths = (const int*)d_in[1];
    const float* targets = (const float*)d_in[2];
    const float* W_sy    = (const float*)d_in[3];
    const float* W_gy    = (const float*)d_in[4];
    const float* b_gy    = (const float*)d_in[5];
    const float* W_yy    = (const float*)d_in[6];
    const float* b_yy    = (const float*)d_in[7];
    const float* W_ys    = (const float*)d_in[8];
    const float* W_ss    = (const float*)d_in[9];
    const float* W_gs    = (const float*)d_in[10];
    const float* b_gs    = (const float*)d_in[11];
    const float* W_se    = (const float*)d_in[12];
    const float* W_he    = (const float*)d_in[13];
    const float* W_fe    = (const float*)d_in[14];
    const float* conv_w  = (const float*)d_in[15];
    const float* conv_b  = (const float*)d_in[16];
    const float* w_ee    = (const float*)d_in[17];
    float* out = (float*)d_out;

    k_init<<<2048, 256>>>(W_se, W_sy, W_ss, W_gy, W_gs);
    // hE = hbatch @ W_he^T : [25600,512]
    k_gemm_big<0><<<dim3(4, 200), 256>>>(hbatch, W_he, nullptr, 1024, 1024, 512, 1024);
    // recpre = targets @ W_ys^T + b_gs : [1920,2048]
    k_gemm_big<1><<<dim3(16, 15), 256>>>(targets, W_ys, b_gs, 4000, 4000, 2048, 4000);

    for (int l = 0; l < LL; l++) {
        k_skinny<0><<<dim3(48, 2), 256>>>(nullptr, nullptr, nullptr);
        k_attn<<<dim3(13, 32), 256>>>(lengths, W_fe, conv_w, conv_b, w_ee);
        k_softmax<<<32, 256>>>();
        k_gaccum<<<dim3(8, 32, 4), 256>>>(hbatch, lengths);
        k_skinny<1><<<dim3(40, 4), 256>>>(nullptr, nullptr, nullptr);
        k_cell<<<32, 512>>>(b_gy, l);
        k_skinny<2><<<dim3(63, 1), 256>>>(W_yy, b_yy, out + (size_t)l * CC);
    }
}

// round 3
// speedup vs baseline: 1.5259x; 1.5259x over previous
#include <cuda_runtime.h>
#include <cstdint>

#define BB 32
#define TT 800
#define LL 60
#define HH 512
#define DD 1024
#define AA 512
#define FCN 16
#define KCV 101
#define CC 4000
#define NSP 8

typedef unsigned long long ull;

// ---------------- static device scratch ----------------
__device__ float g_hE[BB * TT * AA];
__device__ float g_recpre[BB * LL * 2048];
__device__ float g_Wscat[3072 * 512];
__device__ float g_Wgcat[2560 * 1024];
__device__ float g_spart[NSP * BB * 3072];
__device__ float g_gpart[NSP * BB * 2560];
__device__ float g_gp2[NSP * BB * DD];
__device__ float g_e[BB * TT];
__device__ float g_alpha[BB * TT];
__device__ float g_ypre_all[LL * BB * HH];
__device__ float g_s[BB * HH];
__device__ float g_c[BB * HH];

__device__ __forceinline__ void fma2(ull& d, ull a, ull b) {
    asm("fma.rn.f32x2 %0, %1, %2, %0;" : "+l"(d) : "l"(a), "l"(b));
}
__device__ __forceinline__ float2 unpk(ull v) {
    float2 f;
    asm("mov.b64 {%0,%1}, %2;" : "=f"(f.x), "=f"(f.y) : "l"(v));
    return f;
}
__device__ __forceinline__ float tanh_fast(float x) {
    float e2 = __expf(2.f * x);
    return 1.f - 2.f / (e2 + 1.f);
}
__device__ __forceinline__ float sig_acc(float x) {
    return tanhf(0.5f * x) * 0.5f + 0.5f;
}

// ---------------- init ----------------
__global__ void k_init(const float* __restrict__ W_se, const float* __restrict__ W_sy,
                       const float* __restrict__ W_ss, const float* __restrict__ W_gy,
                       const float* __restrict__ W_gs) {
    int i0 = blockIdx.x * blockDim.x + threadIdx.x;
    int st = gridDim.x * blockDim.x;
    for (int i = i0; i < BB * HH; i += st) { g_s[i] = 0.f; g_c[i] = 0.f; }
    for (int i = i0; i < BB * TT; i += st) g_alpha[i] = 0.f;
    for (int i = i0; i < 3072 * 512; i += st) {
        int r = i >> 9, k = i & 511;
        float v;
        if (r < 512)       v = W_se[i];
        else if (r < 1024) v = W_sy[(r - 512) * 512 + k];
        else               v = W_ss[(r - 1024) * 512 + k];
        g_Wscat[i] = v;
    }
    for (int i = i0; i < 2560 * 1024; i += st) {
        int r = i >> 10, k = i & 1023;
        g_Wgcat[i] = (r < 512) ? W_gy[i] : W_gs[(r - 512) * 1024 + k];
    }
}

// ---------------- big GEMM (FFMA2): Out[M,N] = A[M,K] @ W[N,K]^T (+bias) ----------------
// MODE 0: -> g_hE (ldo 512)   MODE 1: -> g_recpre (ldo 2048, +b_gs)
// MODE 2: A = g_ypre_all, -> out[b][l][c] map (+b_yy, N guard 4000)
template <int MODE>
__global__ __launch_bounds__(256) void k_gemm_big(
    const float* __restrict__ A, const float* __restrict__ W,
    const float* __restrict__ bias, float* __restrict__ outx,
    int lda, int ldw, int K) {
    __shared__ __align__(16) float As2[16][264];
    __shared__ __align__(16) float Bs[16][132];
    const float* Ap = (MODE == 2) ? g_ypre_all : A;
    int t = threadIdx.x;
    int n0 = blockIdx.x * 128, m0 = blockIdx.y * 128;
    int tr = t >> 4, tc = t & 15;
    ull acc2[8][4];
#pragma unroll
    for (int i = 0; i < 8; i++)
#pragma unroll
        for (int j = 0; j < 4; j++) acc2[i][j] = 0ull;

    for (int k0 = 0; k0 < K; k0 += 16) {
#pragma unroll
        for (int j = 0; j < 8; j++) {
            int e = t + j * 256;
            int m = e >> 4, k = e & 15;
            float av = Ap[(size_t)(m0 + m) * lda + k0 + k];
            *(float2*)&As2[k][2 * m] = make_float2(av, av);
            int n = n0 + m;
            float wv = 0.f;
            if (MODE != 2 || n < CC) wv = W[(size_t)n * ldw + k0 + k];
            Bs[k][m] = wv;
        }
        __syncthreads();
#pragma unroll
        for (int k = 0; k < 16; k++) {
            ulonglong2 aA = *(const ulonglong2*)&As2[k][tr * 16];
            ulonglong2 aB = *(const ulonglong2*)&As2[k][tr * 16 + 4];
            ulonglong2 aC = *(const ulonglong2*)&As2[k][tr * 16 + 8];
            ulonglong2 aD = *(const ulonglong2*)&As2[k][tr * 16 + 12];
            ulonglong2 b0 = *(const ulonglong2*)&Bs[k][tc * 8];
            ulonglong2 b1 = *(const ulonglong2*)&Bs[k][tc * 8 + 4];
            ull av[8] = {aA.x, aA.y, aB.x, aB.y, aC.x, aC.y, aD.x, aD.y};
            ull bv[4] = {b0.x, b0.y, b1.x, b1.y};
#pragma unroll
            for (int i = 0; i < 8; i++)
#pragma unroll
                for (int j = 0; j < 4; j++) fma2(acc2[i][j], av[i], bv[j]);
        }
        __syncthreads();
    }
#pragma unroll
    for (int i = 0; i < 8; i++) {
        int m = m0 + tr * 8 + i;
        float* orow;
        if (MODE == 0)      orow = &g_hE[(size_t)m * 512];
        else if (MODE == 1) orow = &g_recpre[(size_t)m * 2048];
        else {
            int l = m >> 5, b = m & 31;
            orow = outx + (size_t)b * LL * CC + (size_t)l * CC;
        }
#pragma unroll
        for (int j = 0; j < 4; j++) {
            float2 v = unpk(acc2[i][j]);
            int n = n0 + tc * 8 + 2 * j;
            if (MODE == 2) {
                if (n < CC)     orow[n] = v.x + bias[n];
                if (n + 1 < CC) orow[n + 1] = v.y + bias[n + 1];
            } else if (MODE == 1) {
                orow[n] = v.x + bias[n];
                orow[n + 1] = v.y + bias[n + 1];
            } else {
                orow[n] = v.x;
                orow[n + 1] = v.y;
            }
        }
    }
}

// ---------------- skinny GEMM (FFMA2, M=32, k-split 8) ----------------
// MODE 0: s @ Wscat^T (N=3072,K=512) -> g_spart[z]
// MODE 1: (sum gp2) @ Wgcat^T (N=2560,K=1024) -> g_gpart[z]
template <int MODE>
__global__ __launch_bounds__(128) void k_skinny() {
    constexpr int N = MODE ? 2560 : 3072;
    constexpr int K = MODE ? 1024 : 512;
    constexpr int KS = K / NSP;
    __shared__ __align__(16) float As[32][36];
    __shared__ __align__(16) float Bsd[32][260];
    int t = threadIdx.x, tn = t & 31, tm = t >> 5;
    int n0 = blockIdx.x * 128, z = blockIdx.y;
    const float* W = MODE ? g_Wgcat : g_Wscat;
    float* Out = MODE ? (g_gpart + z * BB * 2560) : (g_spart + z * BB * 3072);
    int kb = z * KS;
    ull acc2[4][4];
#pragma unroll
    for (int p = 0; p < 4; p++)
#pragma unroll
        for (int j = 0; j < 4; j++) acc2[p][j] = 0ull;

    for (int kk = 0; kk < KS; kk += 32) {
        int k0 = kb + kk;
#pragma unroll
        for (int j = 0; j < 8; j++) {
            int e = t + j * 128;
            int m = e >> 5, k = e & 31;
            float v;
            if (MODE == 0) v = g_s[m * 512 + k0 + k];
            else {
                v = 0.f;
#pragma unroll
                for (int p = 0; p < NSP; p++) v += g_gp2[p * BB * DD + m * DD + k0 + k];
            }
            As[k][m] = v;
        }
#pragma unroll
        for (int j = 0; j < 32; j++) {
            int e = t + j * 128;
            int n = e >> 5, k = e & 31;
            float wv = W[(size_t)(n0 + n) * K + k0 + k];
            *(float2*)&Bsd[k][2 * n] = make_float2(wv, wv);
        }
        __syncthreads();
#pragma unroll
        for (int k = 0; k < 32; k++) {
            ulonglong2 aA = *(const ulonglong2*)&As[k][tm * 8];
            ulonglong2 aB = *(const ulonglong2*)&As[k][tm * 8 + 4];
            ull ap[4] = {aA.x, aA.y, aB.x, aB.y};
            ull bd[4];
#pragma unroll
            for (int j = 0; j < 4; j++) bd[j] = *(const ull*)&Bsd[k][2 * (tn + j * 32)];
#pragma unroll
            for (int p = 0; p < 4; p++)
#pragma unroll
                for (int j = 0; j < 4; j++) fma2(acc2[p][j], ap[p], bd[j]);
        }
        __syncthreads();
    }
#pragma unroll
    for (int p = 0; p < 4; p++)
#pragma unroll
        for (int j = 0; j < 4; j++) {
            float2 v = unpk(acc2[p][j]);
            int m = tm * 8 + 2 * p;
            int n = n0 + tn + j * 32;
            Out[m * N + n] = v.x;
            Out[(m + 1) * N + n] = v.y;
        }
}

// ---------------- fused attention scoring ----------------
__global__ __launch_bounds__(256) void k_attn(const int* __restrict__ lengths,
                                              const float* __restrict__ W_fe,
                                              const float* __restrict__ conv_w,
                                              const float* __restrict__ conv_b,
                                              const float* __restrict__ w_ee) {
    __shared__ float sE_s[AA];
    __shared__ float wee_s[AA];
    __shared__ float convw_s[FCN * KCV];
    __shared__ float convb_s[FCN];
    __shared__ float alpha_s[132];
    __shared__ __align__(16) float WfeT[FCN * 516];
    int b = blockIdx.y;
    int t0 = blockIdx.x * 32;
    int tid = threadIdx.x;
    int len = lengths[b];
    if (t0 >= len) {
        if (tid < 32) g_e[b * TT + t0 + tid] = -1e30f;
        return;
    }
    for (int a = tid; a < AA; a += 256) {
        float v = 0.f;
#pragma unroll
        for (int p = 0; p < NSP; p++) v += g_spart[p * BB * 3072 + b * 3072 + a];
        sE_s[a] = v;
        wee_s[a] = w_ee[a];
    }
    for (int i = tid; i < FCN * KCV; i += 256) convw_s[i] = conv_w[i];
    if (tid < FCN) convb_s[tid] = conv_b[tid];
    for (int i = tid; i < AA * FCN; i += 256) {
        int a = i >> 4, f = i & 15;
        WfeT[f * 516 + a] = W_fe[i];
    }
    if (tid < 132) {
        int tg = t0 - 50 + tid;
        alpha_s[tid] = (tg >= 0 && tg < TT) ? g_alpha[b * TT + tg] : 0.f;
    }
    __syncthreads();
    int w = tid >> 5, lane = tid & 31;
    for (int tt = w; tt < 32; tt += 8) {
        int tabs = t0 + tt;
        if (tabs >= len) {
            if (lane == 0) g_e[b * TT + tabs] = -1e30f;
            continue;
        }
        int f = lane & 15, half = lane >> 4;
        float yp = 0.f;
        int ks = half * 51, ke = half ? KCV : 51;
        for (int k = ks; k < ke; k++)
            yp = fmaf(alpha_s[tt + k], convw_s[f * KCV + k], yp);
        yp += __shfl_down_sync(0xffffffffu, yp, 16);
        if (half == 0) yp += convb_s[f];
        float yv[16];
#pragma unroll
        for (int ff = 0; ff < 16; ff++) yv[ff] = __shfl_sync(0xffffffffu, yp, ff);
        const float* hEr = g_hE + ((size_t)b * TT + tabs) * AA;
        float4 v[4];
#pragma unroll
        for (int c = 0; c < 4; c++) {
            float4 h4 = *(const float4*)&hEr[c * 128 + lane * 4];
            const float4 s4 = *(const float4*)&sE_s[c * 128 + lane * 4];
            v[c].x = h4.x + s4.x; v[c].y = h4.y + s4.y;
            v[c].z = h4.z + s4.z; v[c].w = h4.w + s4.w;
        }
#pragma unroll
        for (int ff = 0; ff < 16; ff++) {
            float yf = yv[ff];
#pragma unroll
            for (int c = 0; c < 4; c++) {
                float4 w4 = *(const float4*)&WfeT[ff * 516 + c * 128 + lane * 4];
                v[c].x = fmaf(yf, w4.x, v[c].x);
                v[c].y = fmaf(yf, w4.y, v[c].y);
                v[c].z = fmaf(yf, w4.z, v[c].z);
                v[c].w = fmaf(yf, w4.w, v[c].w);
            }
        }
        float acc = 0.f;
#pragma unroll
        for (int c = 0; c < 4; c++) {
            float4 we = *(const float4*)&wee_s[c * 128 + lane * 4];
            acc = fmaf(tanh_fast(v[c].x), we.x, acc);
            acc = fmaf(tanh_fast(v[c].y), we.y, acc);
            acc = fmaf(tanh_fast(v[c].z), we.z, acc);
            acc = fmaf(tanh_fast(v[c].w), we.w, acc);
        }
#pragma unroll
        for (int off = 16; off; off >>= 1) acc += __shfl_down_sync(0xffffffffu, acc, off);
        if (lane == 0) g_e[b * TT + tabs] = acc;
    }
}

// ---------------- softmax ----------------
__global__ __launch_bounds__(256) void k_softmax() {
    int b = blockIdx.x, tid = threadIdx.x;
    __shared__ float es[TT];
    __shared__ float red[256];
    float mx = -3e38f;
    for (int t2 = tid; t2 < TT; t2 += 256) {
        float v = g_e[b * TT + t2];
        es[t2] = v;
        mx = fmaxf(mx, v);
    }
    red[tid] = mx;
    __syncthreads();
    for (int o = 128; o; o >>= 1) {
        if (tid < o) red[tid] = fmaxf(red[tid], red[tid + o]);
        __syncthreads();
    }
    float M = red[0];
    __syncthreads();
    float sm = 0.f;
    for (int t2 = tid; t2 < TT; t2 += 256) {
        float p = __expf(es[t2] - M);
        es[t2] = p;
        sm += p;
    }
    red[tid] = sm;
    __syncthreads();
    for (int o = 128; o; o >>= 1) {
        if (tid < o) red[tid] += red[tid + o];
        __syncthreads();
    }
    float inv = 1.f / red[0];
    for (int t2 = tid; t2 < TT; t2 += 256) g_alpha[b * TT + t2] = es[t2] * inv;
}

// ---------------- g = alpha @ hbatch (t-split x8 partials) ----------------
__global__ __launch_bounds__(256) void k_gaccum(const float* __restrict__ hbatch,
                                                const int* __restrict__ lengths) {
    int b = blockIdx.x, ts = blockIdx.y;
    int len = lengths[b];
    int t1 = (len * ts) / NSP, t2 = (len * (ts + 1)) / NSP;
    int d = threadIdx.x * 4;
    float4 acc = make_float4(0.f, 0.f, 0.f, 0.f);
    const float* hb = hbatch + (size_t)b * TT * DD + d;
    const float* al = g_alpha + b * TT;
    int t = t1;
    for (; t + 4 <= t2; t += 4) {
        float a0 = al[t], a1 = al[t + 1], a2 = al[t + 2], a3 = al[t + 3];
        float4 h0 = *(const float4*)&hb[(size_t)t * DD];
        float4 h1 = *(const float4*)&hb[(size_t)(t + 1) * DD];
        float4 h2 = *(const float4*)&hb[(size_t)(t + 2) * DD];
        float4 h3 = *(const float4*)&hb[(size_t)(t + 3) * DD];
        acc.x = fmaf(a0, h0.x, fmaf(a1, h1.x, fmaf(a2, h2.x, fmaf(a3, h3.x, acc.x))));
        acc.y = fmaf(a0, h0.y, fmaf(a1, h1.y, fmaf(a2, h2.y, fmaf(a3, h3.y, acc.y))));
        acc.z = fmaf(a0, h0.z, fmaf(a1, h1.z, fmaf(a2, h2.z, fmaf(a3, h3.z, acc.z))));
        acc.w = fmaf(a0, h0.w, fmaf(a1, h1.w, fmaf(a2, h2.w, fmaf(a3, h3.w, acc.w))));
    }
    for (; t < t2; t++) {
        float a0 = al[t];
        float4 h0 = *(const float4*)&hb[(size_t)t * DD];
        acc.x = fmaf(a0, h0.x, acc.x);
        acc.y = fmaf(a0, h0.y, acc.y);
        acc.z = fmaf(a0, h0.z, acc.z);
        acc.w = fmaf(a0, h0.w, acc.w);
    }
    *(float4*)&g_gp2[ts * BB * DD + b * DD + d] = acc;
}

// ---------------- LSTM cell + ypre ----------------
__global__ __launch_bounds__(512) void k_cell(const float* __restrict__ b_gy, int l) {
    int b = blockIdx.x, h = threadIdx.x;
    float gy = 0.f, sy = 0.f;
#pragma unroll
    for (int p = 0; p < NSP; p++) {
        gy += g_gpart[p * BB * 2560 + b * 2560 + h];
        sy += g_spart[p * BB * 3072 + b * 3072 + 512 + h];
    }
    float ypre = tanhf(gy + sy + b_gy[h]);
    g_ypre_all[((size_t)l * BB + b) * HH + h] = ypre;
    float r[4];
#pragma unroll
    for (int q = 0; q < 4; q++) {
        int j = q * 512 + h;
        float v = g_recpre[((size_t)b * LL + l) * 2048 + j];
#pragma unroll
        for (int p = 0; p < NSP; p++) {
            v += g_spart[p * BB * 3072 + b * 3072 + 1024 + j];
            v += g_gpart[p * BB * 2560 + b * 2560 + 512 + j];
        }
        r[q] = v;
    }
    float c = sig_acc(r[1]) * g_c[b * HH + h] + sig_acc(r[0]) * tanhf(r[2]);
    float s = sig_acc(r[3]) * tanhf(c);
    g_c[b * HH + h] = c;
    g_s[b * HH + h] = s;
}

// ---------------- launch ----------------
extern "C" void kernel_launch(void* const* d_in, const int* in_sizes, int n_in,
                              void* d_out, int out_size) {
    const float* hbatch  = (const float*)d_in[0];
    const int*   lengths = (const int*)d_in[1];
    const float* targets = (const float*)d_in[2];
    const float* W_sy    = (const float*)d_in[3];
    const float* W_gy    = (const float*)d_in[4];
    const float* b_gy    = (const float*)d_in[5];
    const float* W_yy    = (const float*)d_in[6];
    const float* b_yy    = (const float*)d_in[7];
    const float* W_ys    = (const float*)d_in[8];
    const float* W_ss    = (const float*)d_in[9];
    const float* W_gs    = (const float*)d_in[10];
    const float* b_gs    = (const float*)d_in[11];
    const float* W_se    = (const float*)d_in[12];
    const float* W_he    = (const float*)d_in[13];
    const float* W_fe    = (const float*)d_in[14];
    const float* conv_w  = (const float*)d_in[15];
    const float* conv_b  = (const float*)d_in[16];
    const float* w_ee    = (const float*)d_in[17];
    float* out = (float*)d_out;

    k_init<<<2048, 256>>>(W_se, W_sy, W_ss, W_gy, W_gs);
    // hE = hbatch @ W_he^T : [25600,512], K=1024
    k_gemm_big<0><<<dim3(4, 200), 256>>>(hbatch, W_he, nullptr, nullptr, 1024, 1024, 1024);
    // recpre = targets @ W_ys^T + b_gs : [1920,2048], K=4000
    k_gemm_big<1><<<dim3(16, 15), 256>>>(targets, W_ys, b_gs, nullptr, 4000, 4000, 4000);

    for (int l = 0; l < LL; l++) {
        k_skinny<0><<<dim3(24, NSP), 128>>>();
        k_attn<<<dim3(25, 32), 256>>>(lengths, W_fe, conv_w, conv_b, w_ee);
        k_softmax<<<32, 256>>>();
        k_gaccum<<<dim3(32, NSP), 256>>>(hbatch, lengths);
        k_skinny<1><<<dim3(20, NSP), 128>>>();
        k_cell<<<32, 512>>>(b_gy, l);
    }
    // y = ypre_all @ W_yy^T + b_yy : [1920,4000], K=512 -> out (mapped)
    k_gemm_big<2><<<dim3(32, 15), 256>>>(nullptr, W_yy, b_yy, out, 512, 512, 512);
}

// round 4
// speedup vs baseline: 1.7492x; 1.1464x over previous
#include <cuda_runtime.h>
#include <cstdint>

#define BB 32
#define TT 800
#define LL 60
#define HH 512
#define DD 1024
#define AA 512
#define FCN 16
#define KCV 101
#define CC 4000
#define NSP 16

typedef unsigned long long ull;

// ---------------- static device scratch ----------------
__device__ float g_hE[BB * TT * AA];
__device__ float g_recpre[BB * LL * 2048];
__device__ float g_Wscat[3072 * 512];
__device__ float g_Wgcat[2560 * 1024];
__device__ float g_spart[NSP * BB * 3072];
__device__ float g_gpart[NSP * BB * 2560];
__device__ float g_gp2[NSP * BB * DD];
__device__ float g_sE[BB * AA];
__device__ float g_g[BB * DD];
__device__ float g_e[BB * TT];
__device__ float g_alpha[BB * TT];
__device__ float g_ypre_all[LL * BB * HH];
__device__ float g_s[BB * HH];
__device__ float g_c[BB * HH];

__device__ __forceinline__ void fma2(ull& d, ull a, ull b) {
    asm("fma.rn.f32x2 %0, %1, %2, %0;" : "+l"(d) : "l"(a), "l"(b));
}
__device__ __forceinline__ ull add2(ull a, ull b) {
    ull r;
    asm("add.rn.f32x2 %0, %1, %2;" : "=l"(r) : "l"(a), "l"(b));
    return r;
}
__device__ __forceinline__ ull pack2(float x) {
    ull r;
    asm("mov.b64 %0, {%1, %1};" : "=l"(r) : "f"(x));
    return r;
}
__device__ __forceinline__ float2 unpk(ull v) {
    float2 f;
    asm("mov.b64 {%0,%1}, %2;" : "=f"(f.x), "=f"(f.y) : "l"(v));
    return f;
}
__device__ __forceinline__ float tanh_fast(float x) {
    float e2 = __expf(2.f * x);
    return 1.f - 2.f / (e2 + 1.f);
}
__device__ __forceinline__ float sig_acc(float x) {
    return tanhf(0.5f * x) * 0.5f + 0.5f;
}

// ---------------- init ----------------
__global__ void k_init(const float* __restrict__ W_se, const float* __restrict__ W_sy,
                       const float* __restrict__ W_ss, const float* __restrict__ W_gy,
                       const float* __restrict__ W_gs) {
    int i0 = blockIdx.x * blockDim.x + threadIdx.x;
    int st = gridDim.x * blockDim.x;
    for (int i = i0; i < BB * HH; i += st) { g_s[i] = 0.f; g_c[i] = 0.f; }
    for (int i = i0; i < BB * TT; i += st) g_alpha[i] = 0.f;
    for (int i = i0; i < 3072 * 512; i += st) {
        int r = i >> 9, k = i & 511;
        float v;
        if (r < 512)       v = W_se[i];
        else if (r < 1024) v = W_sy[(r - 512) * 512 + k];
        else               v = W_ss[(r - 1024) * 512 + k];
        g_Wscat[i] = v;
    }
    for (int i = i0; i < 2560 * 1024; i += st) {
        int r = i >> 10, k = i & 1023;
        g_Wgcat[i] = (r < 512) ? W_gy[i] : W_gs[(r - 512) * 1024 + k];
    }
}

// ---------------- big GEMM (FFMA2, m-pair acc): Out[M,N]=A[M,K]@W[N,K]^T ----------------
// MODE 0: -> g_hE   MODE 1: -> g_recpre (+b_gs)   MODE 2: g_ypre_all -> out (+b_yy)
template <int MODE>
__global__ __launch_bounds__(256) void k_gemm_big(
    const float* __restrict__ A, const float* __restrict__ W,
    const float* __restrict__ bias, float* __restrict__ outx,
    int lda, int ldw, int K) {
    __shared__ __align__(16) float As[16][132];
    __shared__ __align__(16) float Bs[16][132];
    const float* Ap = (MODE == 2) ? g_ypre_all : A;
    int t = threadIdx.x;
    int n0 = blockIdx.x * 128, m0 = blockIdx.y * 128;
    int tr = t >> 4, tc = t & 15;
    ull acc2[4][8];
#pragma unroll
    for (int i = 0; i < 4; i++)
#pragma unroll
        for (int j = 0; j < 8; j++) acc2[i][j] = 0ull;

    for (int k0 = 0; k0 < K; k0 += 16) {
#pragma unroll
        for (int j = 0; j < 8; j++) {
            int e = t + j * 256;
            int m = e >> 4, k = e & 15;
            As[k][m] = Ap[(size_t)(m0 + m) * lda + k0 + k];
            int n = n0 + m;
            float wv = 0.f;
            if (MODE != 2 || n < CC) wv = W[(size_t)n * ldw + k0 + k];
            Bs[k][m] = wv;
        }
        __syncthreads();
#pragma unroll
        for (int k = 0; k < 16; k++) {
            ulonglong2 aA = *(const ulonglong2*)&As[k][tr * 8];
            ulonglong2 aB = *(const ulonglong2*)&As[k][tr * 8 + 4];
            ull ap[4] = {aA.x, aA.y, aB.x, aB.y};
            float4 b0 = *(const float4*)&Bs[k][tc * 8];
            float4 b1 = *(const float4*)&Bs[k][tc * 8 + 4];
            ull bp[8] = {pack2(b0.x), pack2(b0.y), pack2(b0.z), pack2(b0.w),
                         pack2(b1.x), pack2(b1.y), pack2(b1.z), pack2(b1.w)};
#pragma unroll
            for (int i = 0; i < 4; i++)
#pragma unroll
                for (int j = 0; j < 8; j++) fma2(acc2[i][j], ap[i], bp[j]);
        }
        __syncthreads();
    }
    // epilogue: rows m0+tr*8+2mp(+1), cols n0+tc*8 .. +7 contiguous
#pragma unroll
    for (int mp = 0; mp < 4; mp++) {
        float r0[8], r1[8];
#pragma unroll
        for (int j = 0; j < 8; j++) {
            float2 v = unpk(acc2[mp][j]);
            int n = n0 + tc * 8 + j;
            float bv = (MODE == 0) ? 0.f : ((MODE == 2 && n >= CC) ? 0.f : bias[n]);
            r0[j] = v.x + bv;
            r1[j] = v.y + bv;
        }
        int me = m0 + tr * 8 + 2 * mp;
        int nn = n0 + tc * 8;
#pragma unroll
        for (int rr = 0; rr < 2; rr++) {
            int m = me + rr;
            const float* src = rr ? r1 : r0;
            float* orow;
            if (MODE == 0)      orow = &g_hE[(size_t)m * 512];
            else if (MODE == 1) orow = &g_recpre[(size_t)m * 2048];
            else {
                int l = m >> 5, b = m & 31;
                orow = outx + (size_t)b * LL * CC + (size_t)l * CC;
            }
            if (MODE != 2 || nn + 7 < CC) {
                *(float4*)&orow[nn] = make_float4(src[0], src[1], src[2], src[3]);
                *(float4*)&orow[nn + 4] = make_float4(src[4], src[5], src[6], src[7]);
            } else {
#pragma unroll
                for (int j = 0; j < 8; j++)
                    if (nn + j < CC) orow[nn + j] = src[j];
            }
        }
    }
}

// ---------------- skinny GEMM: thread-per-n streaming, k-split 16 ----------------
// MODE 0: s @ Wscat^T (N=3072,K=512) -> g_spart[z]
// MODE 1: g @ Wgcat^T (N=2560,K=1024) -> g_gpart[z]
template <int MODE>
__global__ __launch_bounds__(256) void k_skinny() {
    constexpr int N = MODE ? 2560 : 3072;
    constexpr int K = MODE ? 1024 : 512;
    constexpr int KS = K / NSP;
    __shared__ __align__(16) float As[KS][36];
    int tid = threadIdx.x;
    int n = blockIdx.x * 256 + tid;
    int z = blockIdx.y, kb = z * KS;
    const float* W = MODE ? g_Wgcat : g_Wscat;
    const float* Ain = MODE ? g_g : g_s;
    float* Out = MODE ? (g_gpart + z * BB * 2560) : (g_spart + z * BB * 3072);
    for (int i = tid; i < 32 * KS; i += 256) {
        int m = i / KS, k = i % KS;
        As[k][m] = Ain[m * K + kb + k];
    }
    __syncthreads();
    ull acc[16];
#pragma unroll
    for (int mp = 0; mp < 16; mp++) acc[mp] = 0ull;
    const float* Wr = &W[(size_t)n * K + kb];
#pragma unroll 8
    for (int k4 = 0; k4 < KS / 4; k4++) {
        float4 w4 = *(const float4*)&Wr[k4 * 4];
        float wf[4] = {w4.x, w4.y, w4.z, w4.w};
#pragma unroll
        for (int q = 0; q < 4; q++) {
            ull wp = pack2(wf[q]);
            int k = k4 * 4 + q;
#pragma unroll
            for (int mp = 0; mp < 16; mp++) {
                ull a = *(const ull*)&As[k][2 * mp];
                fma2(acc[mp], a, wp);
            }
        }
    }
#pragma unroll
    for (int mp = 0; mp < 16; mp++) {
        float2 v = unpk(acc[mp]);
        Out[(2 * mp) * N + n] = v.x;
        Out[(2 * mp + 1) * N + n] = v.y;
    }
}

// ---------------- tiny reductions over k-split partials ----------------
__global__ void k_sesum() {
    int b = blockIdx.x, a = threadIdx.x;
    float v = 0.f;
#pragma unroll
    for (int p = 0; p < NSP; p++) v += g_spart[p * BB * 3072 + b * 3072 + a];
    g_sE[b * AA + a] = v;
}
__global__ void k_gsum() {
    int b = blockIdx.x, d = threadIdx.x * 4;
    float4 acc = make_float4(0.f, 0.f, 0.f, 0.f);
#pragma unroll
    for (int p = 0; p < NSP; p++) {
        float4 x = *(const float4*)&g_gp2[p * BB * DD + b * DD + d];
        acc.x += x.x; acc.y += x.y; acc.z += x.z; acc.w += x.w;
    }
    *(float4*)&g_g[b * DD + d] = acc;
}

// ---------------- fused attention scoring ----------------
__global__ __launch_bounds__(256) void k_attn(const int* __restrict__ lengths,
                                              const float* __restrict__ W_fe,
                                              const float* __restrict__ conv_w,
                                              const float* __restrict__ conv_b,
                                              const float* __restrict__ w_ee) {
    __shared__ float sE_s[AA];
    __shared__ float wee_s[AA];
    __shared__ float convw_s[FCN * KCV];
    __shared__ float convb_s[FCN];
    __shared__ float alpha_s[132];
    __shared__ __align__(16) float WfeT[FCN * 516];
    int b = blockIdx.y;
    int t0 = blockIdx.x * 32;
    int tid = threadIdx.x;
    int len = lengths[b];
    if (t0 >= len) {
        if (tid < 32) g_e[b * TT + t0 + tid] = -1e30f;
        return;
    }
    for (int a = tid; a < AA; a += 256) {
        sE_s[a] = g_sE[b * AA + a];
        wee_s[a] = w_ee[a];
    }
    for (int i = tid; i < FCN * KCV; i += 256) convw_s[i] = conv_w[i];
    if (tid < FCN) convb_s[tid] = conv_b[tid];
    for (int i = tid; i < AA * FCN; i += 256) {
        int a = i >> 4, f = i & 15;
        WfeT[f * 516 + a] = W_fe[i];
    }
    if (tid < 132) {
        int tg = t0 - 50 + tid;
        alpha_s[tid] = (tg >= 0 && tg < TT) ? g_alpha[b * TT + tg] : 0.f;
    }
    __syncthreads();
    int w = tid >> 5, lane = tid & 31;
    for (int tt = w; tt < 32; tt += 8) {
        int tabs = t0 + tt;
        if (tabs >= len) {
            if (lane == 0) g_e[b * TT + tabs] = -1e30f;
            continue;
        }
        int f = lane & 15, half = lane >> 4;
        float yp = 0.f;
        int ks = half * 51, ke = half ? KCV : 51;
        for (int k = ks; k < ke; k++)
            yp = fmaf(alpha_s[tt + k], convw_s[f * KCV + k], yp);
        yp += __shfl_down_sync(0xffffffffu, yp, 16);
        if (half == 0) yp += convb_s[f];
        ull yp2[16];
#pragma unroll
        for (int ff = 0; ff < 16; ff++) yp2[ff] = pack2(__shfl_sync(0xffffffffu, yp, ff));
        const float* hEr = g_hE + ((size_t)b * TT + tabs) * AA;
        ull v2[8];
#pragma unroll
        for (int c = 0; c < 4; c++) {
            ulonglong2 h2 = *(const ulonglong2*)&hEr[c * 128 + lane * 4];
            ulonglong2 s2 = *(const ulonglong2*)&sE_s[c * 128 + lane * 4];
            v2[2 * c] = add2(h2.x, s2.x);
            v2[2 * c + 1] = add2(h2.y, s2.y);
        }
#pragma unroll
        for (int ff = 0; ff < 16; ff++) {
#pragma unroll
            for (int c = 0; c < 4; c++) {
                ulonglong2 w2 = *(const ulonglong2*)&WfeT[ff * 516 + c * 128 + lane * 4];
                fma2(v2[2 * c], yp2[ff], w2.x);
                fma2(v2[2 * c + 1], yp2[ff], w2.y);
            }
        }
        float acc = 0.f;
#pragma unroll
        for (int c = 0; c < 4; c++) {
            float4 we = *(const float4*)&wee_s[c * 128 + lane * 4];
            float2 a0 = unpk(v2[2 * c]);
            float2 a1 = unpk(v2[2 * c + 1]);
            acc = fmaf(tanh_fast(a0.x), we.x, acc);
            acc = fmaf(tanh_fast(a0.y), we.y, acc);
            acc = fmaf(tanh_fast(a1.x), we.z, acc);
            acc = fmaf(tanh_fast(a1.y), we.w, acc);
        }
#pragma unroll
        for (int off = 16; off; off >>= 1) acc += __shfl_down_sync(0xffffffffu, acc, off);
        if (lane == 0) g_e[b * TT + tabs] = acc;
    }
}

// ---------------- fused softmax + g = alpha @ hbatch (t-split x16) ----------------
__global__ __launch_bounds__(256) void k_gaccum(const float* __restrict__ hbatch,
                                                const int* __restrict__ lengths) {
    int b = blockIdx.x, ts = blockIdx.y;
    int tid = threadIdx.x;
    __shared__ float es[TT];
    __shared__ float red[256];
    float mx = -3e38f;
    for (int t2 = tid; t2 < TT; t2 += 256) {
        float v = g_e[b * TT + t2];
        es[t2] = v;
        mx = fmaxf(mx, v);
    }
    red[tid] = mx;
    __syncthreads();
    for (int o = 128; o; o >>= 1) {
        if (tid < o) red[tid] = fmaxf(red[tid], red[tid + o]);
        __syncthreads();
    }
    float M = red[0];
    __syncthreads();
    float sm = 0.f;
    for (int t2 = tid; t2 < TT; t2 += 256) {
        float p = __expf(es[t2] - M);
        es[t2] = p;
        sm += p;
    }
    red[tid] = sm;
    __syncthreads();
    for (int o = 128; o; o >>= 1) {
        if (tid < o) red[tid] += red[tid + o];
        __syncthreads();
    }
    float inv = 1.f / red[0];
    __syncthreads();
    for (int t2 = tid; t2 < TT; t2 += 256) es[t2] *= inv;
    __syncthreads();
    if (ts == 0)
        for (int t2 = tid; t2 < TT; t2 += 256) g_alpha[b * TT + t2] = es[t2];

    int len = lengths[b];
    int t1 = (len * ts) / NSP, t2e = (len * (ts + 1)) / NSP;
    int d = tid * 4;
    float4 acc = make_float4(0.f, 0.f, 0.f, 0.f);
    const float* hb = hbatch + (size_t)b * TT * DD + d;
    int t = t1;
    for (; t + 4 <= t2e; t += 4) {
        float a0 = es[t], a1 = es[t + 1], a2 = es[t + 2], a3 = es[t + 3];
        float4 h0 = *(const float4*)&hb[(size_t)t * DD];
        float4 h1 = *(const float4*)&hb[(size_t)(t + 1) * DD];
        float4 h2 = *(const float4*)&hb[(size_t)(t + 2) * DD];
        float4 h3 = *(const float4*)&hb[(size_t)(t + 3) * DD];
        acc.x = fmaf(a0, h0.x, fmaf(a1, h1.x, fmaf(a2, h2.x, fmaf(a3, h3.x, acc.x))));
        acc.y = fmaf(a0, h0.y, fmaf(a1, h1.y, fmaf(a2, h2.y, fmaf(a3, h3.y, acc.y))));
        acc.z = fmaf(a0, h0.z, fmaf(a1, h1.z, fmaf(a2, h2.z, fmaf(a3, h3.z, acc.z))));
        acc.w = fmaf(a0, h0.w, fmaf(a1, h1.w, fmaf(a2, h2.w, fmaf(a3, h3.w, acc.w))));
    }
    for (; t < t2e; t++) {
        float a0 = es[t];
        float4 h0 = *(const float4*)&hb[(size_t)t * DD];
        acc.x = fmaf(a0, h0.x, acc.x);
        acc.y = fmaf(a0, h0.y, acc.y);
        acc.z = fmaf(a0, h0.z, acc.z);
        acc.w = fmaf(a0, h0.w, acc.w);
    }
    *(float4*)&g_gp2[ts * BB * DD + b * DD + d] = acc;
}

// ---------------- LSTM cell + ypre ----------------
__global__ __launch_bounds__(512) void k_cell(const float* __restrict__ b_gy, int l) {
    int b = blockIdx.x, h = threadIdx.x;
    float gy = 0.f, sy = 0.f;
#pragma unroll
    for (int p = 0; p < NSP; p++) {
        gy += g_gpart[p * BB * 2560 + b * 2560 + h];
        sy += g_spart[p * BB * 3072 + b * 3072 + 512 + h];
    }
    float ypre = tanhf(gy + sy + b_gy[h]);
    g_ypre_all[((size_t)l * BB + b) * HH + h] = ypre;
    float r[4];
#pragma unroll
    for (int q = 0; q < 4; q++) {
        int j = q * 512 + h;
        float v = g_recpre[((size_t)b * LL + l) * 2048 + j];
#pragma unroll
        for (int p = 0; p < NSP; p++) {
            v += g_spart[p * BB * 3072 + b * 3072 + 1024 + j];
            v += g_gpart[p * BB * 2560 + b * 2560 + 512 + j];
        }
        r[q] = v;
    }
    float c = sig_acc(r[1]) * g_c[b * HH + h] + sig_acc(r[0]) * tanhf(r[2]);
    float s = sig_acc(r[3]) * tanhf(c);
    g_c[b * HH + h] = c;
    g_s[b * HH + h] = s;
}

// ---------------- launch ----------------
extern "C" void kernel_launch(void* const* d_in, const int* in_sizes, int n_in,
                              void* d_out, int out_size) {
    const float* hbatch  = (const float*)d_in[0];
    const int*   lengths = (const int*)d_in[1];
    const float* targets = (const float*)d_in[2];
    const float* W_sy    = (const float*)d_in[3];
    const float* W_gy    = (const float*)d_in[4];
    const float* b_gy    = (const float*)d_in[5];
    const float* W_yy    = (const float*)d_in[6];
    const float* b_yy    = (const float*)d_in[7];
    const float* W_ys    = (const float*)d_in[8];
    const float* W_ss    = (const float*)d_in[9];
    const float* W_gs    = (const float*)d_in[10];
    const float* b_gs    = (const float*)d_in[11];
    const float* W_se    = (const float*)d_in[12];
    const float* W_he    = (const float*)d_in[13];
    const float* W_fe    = (const float*)d_in[14];
    const float* conv_w  = (const float*)d_in[15];
    const float* conv_b  = (const float*)d_in[16];
    const float* w_ee    = (const float*)d_in[17];
    float* out = (float*)d_out;

    k_init<<<2048, 256>>>(W_se, W_sy, W_ss, W_gy, W_gs);
    // hE = hbatch @ W_he^T : [25600,512], K=1024
    k_gemm_big<0><<<dim3(4, 200), 256>>>(hbatch, W_he, nullptr, nullptr, 1024, 1024, 1024);
    // recpre = targets @ W_ys^T + b_gs : [1920,2048], K=4000
    k_gemm_big<1><<<dim3(16, 15), 256>>>(targets, W_ys, b_gs, nullptr, 4000, 4000, 4000);

    for (int l = 0; l < LL; l++) {
        k_skinny<0><<<dim3(12, NSP), 256>>>();
        k_sesum<<<32, 512>>>();
        k_attn<<<dim3(25, 32), 256>>>(lengths, W_fe, conv_w, conv_b, w_ee);
        k_gaccum<<<dim3(32, NSP), 256>>>(hbatch, lengths);
        k_gsum<<<32, 256>>>();
        k_skinny<1><<<dim3(10, NSP), 256>>>();
        k_cell<<<32, 512>>>(b_gy, l);
    }
    // y = ypre_all @ W_yy^T + b_yy : [1920,4000], K=512 -> out (mapped)
    k_gemm_big<2><<<dim3(32, 15), 256>>>(nullptr, W_yy, b_yy, out, 512, 512, 512);
}